// round 12
// baseline (speedup 1.0000x reference)
#include <cuda_runtime.h>
#include <cuda_fp16.h>
#include <cstdint>

#define NN 1024
#define H2 60
#define DEP 10
#define DOUT 70
#define NTYPE 50

// fp16 T layout per i: main = dims 0..63, 50 rows x 64 halfs (128B rows);
// tail = dims 64..69 (+2 pad), 50 rows x 8 halfs (16B rows).
#define TPI 3600
#define BUFH 3680             // halfs per i-slot in SMEM (7360B)
#define SLOTB 7360
#define MAIN_SENT_B 6400u
#define TAIL_BASE_B 6528

__device__ __half g_Th[NN * TPI];    // 7.37 MB — L2-resident

// tanh(x) = 1 - 2/(exp(2x)+1), via SFU ex2/rcp.
__device__ __forceinline__ float fast_tanh(float x) {
    float e, r;
    asm("ex2.approx.f32 %0, %1;" : "=f"(e) : "f"(x * 2.885390082f));
    asm("rcp.approx.f32 %0, %1;" : "=f"(r) : "f"(e + 1.0f));
    return fmaf(-2.0f, r, 1.0f);
}

// ---------------------------------------------------------------------------
// Kernel R: 640 threads = 4 independent groups x 160 (5 warps). Block first
// computes eWb (3500 floats) into SMEM (shared by all groups), then each
// group owns row i = B*4+grp: warp-private histogram banks + named barriers,
// hW via __ldg, T table (fp16 split), s_in, zero s_out.
// ---------------------------------------------------------------------------
__global__ __launch_bounds__(640) void row_kernel(
    const float* __restrict__ h,
    const float* __restrict__ emb,
    const float* __restrict__ W,
    const float* __restrict__ bvec,
    const int* __restrict__ matrix,
    const int* __restrict__ mask,
    float* __restrict__ out)
{
    const int tid = threadIdx.x;
    const int grp = tid / 160;
    const int gtid = tid - grp * 160;
    const int w = tid >> 5;            // global warp id 0..19
    const int lane = tid & 31;
    const int i = blockIdx.x * 4 + grp;
    const int bar = grp + 1;

    __shared__ int   cnt[20][64];      // warp-private histogram banks
    __shared__ float sP[4][72];
    __shared__ float ewb[NTYPE * DOUT];  // 3500 floats

    // block-wide: eWb table + zero histogram banks
    cnt[w][lane] = 0;
    cnt[w][lane + 32] = 0;
    for (int k = tid; k < NTYPE * DOUT; k += 640) {
        int t = k / DOUT, f = k - t * DOUT;
        float s = __ldg(bvec + f);
        #pragma unroll
        for (int c = 0; c < DEP; c++)
            s = fmaf(__ldg(emb + t * DEP + c), __ldg(W + (H2 + c) * DOUT + f), s);
        ewb[k] = s;
    }
    __syncthreads();

    // masked type histogram over row i (int4 loads)
    {
        const int4* m4 = (const int4*)(matrix + (size_t)i * 2 * NN);
        const int4* k4 = (const int4*)(mask   + (size_t)i * 2 * NN);
        for (int e = gtid; e < 512; e += 160) {
            int4 mm = m4[e];
            int4 kk = k4[e];
            if (kk.x) atomicAdd(&cnt[w][mm.x], 1);
            if (kk.y) atomicAdd(&cnt[w][mm.y], 1);
            if (kk.z) atomicAdd(&cnt[w][mm.z], 1);
            if (kk.w) atomicAdd(&cnt[w][mm.w], 1);
        }
    }
    asm volatile("bar.sync %0, 160;" :: "r"(bar) : "memory");

    // reduce the group's 5 banks into bank grp*5
    const int b0 = grp * 5;
    if (gtid < NTYPE) {
        int s = cnt[b0][gtid] + cnt[b0 + 1][gtid] + cnt[b0 + 2][gtid]
              + cnt[b0 + 3][gtid] + cnt[b0 + 4][gtid];
        cnt[b0][gtid] = s;
    }
    asm volatile("bar.sync %0, 160;" :: "r"(bar) : "memory");

    // heavy phase: 140 active threads, (shalf, f), t split in halves of 25
    const int shalf = gtid / DOUT;
    const int f = gtid - shalf * DOUT;
    float acc = 0.f;
    if (shalf < 2) {
        float hw = 0.f;
        #pragma unroll 6
        for (int c = 0; c < H2; c++)
            hw = fmaf(__ldg(h + i * H2 + c), __ldg(W + c * DOUT + f), hw);

        __half* Tb = g_Th + (size_t)i * TPI;
        const int t0 = shalf * 25, t1 = t0 + 25;
        #pragma unroll 5
        for (int t = t0; t < t1; t++) {
            float v = fast_tanh(hw + ewb[t * DOUT + f]);
            if (f < 64) Tb[t * 64 + f] = __float2half_rn(v);
            else        Tb[3200 + t * 8 + (f - 64)] = __float2half_rn(v);
            acc = fmaf((float)cnt[b0][t], v, acc);
        }
        if (shalf == 1) sP[grp][f] = acc;
    }
    asm volatile("bar.sync %0, 160;" :: "r"(bar) : "memory");
    if (shalf == 0) {
        out[i * DOUT + f] = acc + sP[grp][f];   // s_in (fp32)
        out[NN * DOUT + i * DOUT + f] = 0.f;    // zero s_out for kernel C
    }
}

// ---------------------------------------------------------------------------
// Kernel C: s_out gather. Grid (8 j-tiles of 128, 37 i-tiles) = 296 blocks,
// 2 CTAs/SM. Dynamic SMEM: ping-pong buffers of FOUR i-slots each + codes.
// cp.async staging, int4 code broadcasts, HADD2 pair-sum, branch-free
// sentinel rows.
// ---------------------------------------------------------------------------
#define IT 28
#define IPS 4
#define CTHREADS 512
// dynamic smem: 2 buffers x IPS slots x 7360B, then codes 2 x IPS*128 ints
#define COL_TBYTES (2 * IPS * SLOTB)
#define COL_SMEM (COL_TBYTES + 2 * IPS * 128 * 4)

__device__ __forceinline__ void cp16(unsigned dst, const void* src) {
    asm volatile("cp.async.cg.shared.global [%0], [%1], 16;" :: "r"(dst), "l"(src));
}

// stage IPS i-slots (per slot: main 400 cp16 + tail 50 cp16)
__device__ __forceinline__ void stageN(unsigned dst, const char* src, int tid) {
    #pragma unroll
    for (int s = 0; s < IPS; s++) {
        if (tid < 400) cp16(dst + s * SLOTB + tid * 16, src + s * 7200 + tid * 16);
        else if (tid < 450) cp16(dst + s * SLOTB + TAIL_BASE_B + (tid - 400) * 16,
                                 src + s * 7200 + 6400 + (tid - 400) * 16);
    }
}

__global__ __launch_bounds__(CTHREADS, 2) void col_kernel(
    const int* __restrict__ matrix,
    const int* __restrict__ mask,
    float* __restrict__ sout)
{
    extern __shared__ __align__(16) char dyn[];
    char* tbuf = dyn;                               // 2 x IPS slots
    int*  codes = (int*)(dyn + COL_TBYTES);         // [2][IPS*128]

    const int jbase = blockIdx.x * 128;
    const int i0 = blockIdx.y * IT;
    const int i1 = min(i0 + IT, NN);
    const int nst = (i1 - i0) / IPS;    // 7 (or 4 for the clipped last tile)
    const int tid = threadIdx.x;
    const int w = tid >> 5, lane = tid & 31;
    const int g = lane >> 2, p = lane & 3;

    float2 a0[8];
    float2 a1[2];
    #pragma unroll
    for (int q = 0; q < 8; q++) a0[q] = make_float2(0.f, 0.f);
    a1[0] = make_float2(0.f, 0.f);
    a1[1] = make_float2(0.f, 0.f);

    // zero sentinel words: per slot, main = words [1600,1632), tail = [1832,1836)
    for (int z = tid; z < 2 * IPS * 36; z += CTHREADS) {
        int b = z / (IPS * 36), rest = z - b * (IPS * 36);
        int s = rest / 36, k = rest - s * 36;
        int word = (k < 32) ? (1600 + k) : (1832 + (k - 32));
        ((unsigned*)(tbuf + b * IPS * SLOTB))[s * 1840 + word] = 0u;
    }

    const char* tb0 = tbuf;
    const char* tb1 = tbuf + IPS * SLOTB;
    const unsigned ts0 = (unsigned)__cvta_generic_to_shared(tb0);
    const unsigned ts1 = (unsigned)__cvta_generic_to_shared(tb1);

    const int2* m2 = (const int2*)matrix;
    const int2* k2 = (const int2*)mask;

    // prologue: stage (i0 .. i0+3)
    stageN(ts0, (const char*)(g_Th + (size_t)i0 * TPI), tid);
    asm volatile("cp.async.commit_group;");

    int pcode;
    {
        int ii = tid >> 7, jj = tid & 127;
        size_t idx = (size_t)(i0 + ii) * NN + jbase + jj;
        int2 tt = m2[idx];
        int2 km = k2[idx];
        pcode = (km.x ? (tt.x << 7) : (int)MAIN_SENT_B) |
                ((km.y ? (tt.y << 7) : (int)MAIN_SENT_B) << 16);
    }

    for (int st = 0; st < nst; st++) {
        const int buf = st & 1;
        const char* Tbb = buf ? tb1 : tb0;
        int* cbuf = codes + buf * (IPS * 128);

        asm volatile("cp.async.wait_group 0;" ::: "memory");  // stage landed
        cbuf[tid] = pcode;
        __syncthreads();

        if (st + 1 < nst) {
            const int inext = i0 + IPS * (st + 1);
            stageN(buf ? ts0 : ts1, (const char*)(g_Th + (size_t)inext * TPI), tid);
            asm volatile("cp.async.commit_group;");
            int ii = tid >> 7, jj = tid & 127;
            size_t idx = (size_t)(inext + ii) * NN + jbase + jj;
            int2 tt = m2[idx];
            int2 km = k2[idx];
            pcode = (km.x ? (tt.x << 7) : (int)MAIN_SENT_B) |
                    ((km.y ? (tt.y << 7) : (int)MAIN_SENT_B) << 16);
        }

        // gather all IPS slots of this stage
        #pragma unroll
        for (int s2 = 0; s2 < IPS; s2++) {
            const char* Tb = Tbb + s2 * SLOTB;
            const int4* c4 = (const int4*)(cbuf + s2 * 128 + w * 8);
            int4 cA = c4[0];          // broadcast LDS.128
            int4 cB = c4[1];
            unsigned cq[8] = {(unsigned)cA.x, (unsigned)cA.y, (unsigned)cA.z, (unsigned)cA.w,
                              (unsigned)cB.x, (unsigned)cB.y, (unsigned)cB.z, (unsigned)cB.w};
            const char* mb = Tb + lane * 4;
            #pragma unroll
            for (int q = 0; q < 8; q++) {
                unsigned cc = cq[q];
                unsigned o0 = cc & 0xFFFFu;
                unsigned o1 = cc >> 16;
                __half2 h0 = *(const __half2*)(mb + o0);
                __half2 h1 = *(const __half2*)(mb + o1);
                float2 v = __half22float2(__hadd2(h0, h1));
                a0[q].x += v.x;
                a0[q].y += v.y;
            }
            // tail: slots s = r*8+g; lane reads pair p of row t(s)
            #pragma unroll
            for (int r = 0; r < 2; r++) {
                int s = r * 8 + g;
                unsigned cc = cq[s >> 1];
                unsigned c16 = (s & 1) ? (cc >> 16) : (cc & 0xFFFFu);
                unsigned t = c16 >> 7;           // type, or 50 for sentinel
                float2 v = __half22float2(*(const __half2*)(Tb + TAIL_BASE_B + t * 16 + p * 4));
                a1[r].x += v.x;
                a1[r].y += v.y;
            }
        }
    }

    // epilogue: combine partials across the 37 i-tiles
    #pragma unroll
    for (int q = 0; q < 8; q++) {
        int j = jbase + w * 8 + q;
        float* base = sout + (size_t)j * DOUT;
        asm volatile("red.global.add.v2.f32 [%0], {%1, %2};"
                     :: "l"(base + 2 * lane), "f"(a0[q].x), "f"(a0[q].y) : "memory");
    }
    if (p < 3) {
        #pragma unroll
        for (int r = 0; r < 2; r++) {
            int s = r * 8 + g;
            int j = jbase + w * 8 + (s >> 1);
            float* base = sout + (size_t)j * DOUT + 64 + 2 * p;
            asm volatile("red.global.add.v2.f32 [%0], {%1, %2};"
                         :: "l"(base), "f"(a1[r].x), "f"(a1[r].y) : "memory");
        }
    }
}

// ---------------------------------------------------------------------------
extern "C" void kernel_launch(void* const* d_in, const int* in_sizes, int n_in,
                              void* d_out, int out_size)
{
    const float* h      = (const float*)d_in[0];
    const float* emb    = (const float*)d_in[1];
    const float* W      = (const float*)d_in[2];
    const float* bvec   = (const float*)d_in[3];
    const int*   matrix = (const int*)d_in[4];
    const int*   mask   = (const int*)d_in[5];
    float* out = (float*)d_out;

    cudaFuncSetAttribute(col_kernel,
                         cudaFuncAttributeMaxDynamicSharedMemorySize, COL_SMEM);

    row_kernel<<<NN / 4, 640>>>(h, emb, W, bvec, matrix, mask, out);
    col_kernel<<<dim3(8, 37), CTHREADS, COL_SMEM>>>(matrix, mask, out + NN * DOUT);
}

// round 13
// speedup vs baseline: 1.0074x; 1.0074x over previous
#include <cuda_runtime.h>
#include <cuda_fp16.h>
#include <cstdint>

#define NN 1024
#define H2 60
#define DEP 10
#define DOUT 70
#define NTYPE 50

// fp16 T layout per i: main = dims 0..63, 50 rows x 64 halfs (128B rows);
// tail = dims 64..69 (+2 pad), 50 rows x 8 halfs (16B rows).
#define TPI 3600
#define BUFH 3680             // halfs per i-slot in SMEM (7360B)
#define SLOTB 7360
#define MAIN_SENT_B 6400u
#define TAIL_BASE_B 6528

__device__ __half g_Th[NN * TPI];    // 7.37 MB — L2-resident

// tanh(x) = 1 - 2/(exp(2x)+1), via SFU ex2/rcp.
__device__ __forceinline__ float fast_tanh(float x) {
    float e, r;
    asm("ex2.approx.f32 %0, %1;" : "=f"(e) : "f"(x * 2.885390082f));
    asm("rcp.approx.f32 %0, %1;" : "=f"(r) : "f"(e + 1.0f));
    return fmaf(-2.0f, r, 1.0f);
}

// ---------------------------------------------------------------------------
// Kernel R: 640 threads = 4 independent groups x 160 (5 warps). Block first
// computes eWb (3500 floats) into SMEM (shared by all groups), then each
// group owns row i = B*4+grp: warp-private histogram banks + named barriers,
// hW via __ldg, T table (fp16 split), s_in, zero s_out.
// ---------------------------------------------------------------------------
__global__ __launch_bounds__(640) void row_kernel(
    const float* __restrict__ h,
    const float* __restrict__ emb,
    const float* __restrict__ W,
    const float* __restrict__ bvec,
    const int* __restrict__ matrix,
    const int* __restrict__ mask,
    float* __restrict__ out)
{
    const int tid = threadIdx.x;
    const int grp = tid / 160;
    const int gtid = tid - grp * 160;
    const int w = tid >> 5;            // global warp id 0..19
    const int lane = tid & 31;
    const int i = blockIdx.x * 4 + grp;
    const int bar = grp + 1;

    __shared__ int   cnt[20][64];      // warp-private histogram banks
    __shared__ float sP[4][72];
    __shared__ float ewb[NTYPE * DOUT];  // 3500 floats

    // block-wide: eWb table + zero histogram banks
    cnt[w][lane] = 0;
    cnt[w][lane + 32] = 0;
    for (int k = tid; k < NTYPE * DOUT; k += 640) {
        int t = k / DOUT, f = k - t * DOUT;
        float s = __ldg(bvec + f);
        #pragma unroll
        for (int c = 0; c < DEP; c++)
            s = fmaf(__ldg(emb + t * DEP + c), __ldg(W + (H2 + c) * DOUT + f), s);
        ewb[k] = s;
    }
    __syncthreads();

    // masked type histogram over row i (int4 loads)
    {
        const int4* m4 = (const int4*)(matrix + (size_t)i * 2 * NN);
        const int4* k4 = (const int4*)(mask   + (size_t)i * 2 * NN);
        for (int e = gtid; e < 512; e += 160) {
            int4 mm = m4[e];
            int4 kk = k4[e];
            if (kk.x) atomicAdd(&cnt[w][mm.x], 1);
            if (kk.y) atomicAdd(&cnt[w][mm.y], 1);
            if (kk.z) atomicAdd(&cnt[w][mm.z], 1);
            if (kk.w) atomicAdd(&cnt[w][mm.w], 1);
        }
    }
    asm volatile("bar.sync %0, 160;" :: "r"(bar) : "memory");

    // reduce the group's 5 banks into bank grp*5
    const int b0 = grp * 5;
    if (gtid < NTYPE) {
        int s = cnt[b0][gtid] + cnt[b0 + 1][gtid] + cnt[b0 + 2][gtid]
              + cnt[b0 + 3][gtid] + cnt[b0 + 4][gtid];
        cnt[b0][gtid] = s;
    }
    asm volatile("bar.sync %0, 160;" :: "r"(bar) : "memory");

    // heavy phase: 140 active threads, (shalf, f), t split in halves of 25
    const int shalf = gtid / DOUT;
    const int f = gtid - shalf * DOUT;
    float acc = 0.f;
    if (shalf < 2) {
        float hw = 0.f;
        #pragma unroll 6
        for (int c = 0; c < H2; c++)
            hw = fmaf(__ldg(h + i * H2 + c), __ldg(W + c * DOUT + f), hw);

        __half* Tb = g_Th + (size_t)i * TPI;
        const int t0 = shalf * 25, t1 = t0 + 25;
        #pragma unroll 5
        for (int t = t0; t < t1; t++) {
            float v = fast_tanh(hw + ewb[t * DOUT + f]);
            if (f < 64) Tb[t * 64 + f] = __float2half_rn(v);
            else        Tb[3200 + t * 8 + (f - 64)] = __float2half_rn(v);
            acc = fmaf((float)cnt[b0][t], v, acc);
        }
        if (shalf == 1) sP[grp][f] = acc;
    }
    asm volatile("bar.sync %0, 160;" :: "r"(bar) : "memory");
    if (shalf == 0) {
        out[i * DOUT + f] = acc + sP[grp][f];   // s_in (fp32)
        out[NN * DOUT + i * DOUT + f] = 0.f;    // zero s_out for kernel C
    }
}

// ---------------------------------------------------------------------------
// Kernel C: s_out gather — R9-proven IPS=2 static-SMEM structure (no spills),
// with codes read as int4 broadcasts. Grid (8 j-tiles of 128, 37 i-tiles),
// 2 CTAs/SM, cp.async ping-pong of 2 i-slots, HADD2 pair-sum, sentinels.
// ---------------------------------------------------------------------------
#define IT 28
#define CTHREADS 512

__device__ __forceinline__ void cp16(unsigned dst, const void* src) {
    asm volatile("cp.async.cg.shared.global [%0], [%1], 16;" :: "r"(dst), "l"(src));
}

__device__ __forceinline__ void stage2(unsigned dst, const char* src, int tid) {
    #pragma unroll
    for (int s = 0; s < 2; s++) {
        if (tid < 400) cp16(dst + s * SLOTB + tid * 16, src + s * 7200 + tid * 16);
        else if (tid < 450) cp16(dst + s * SLOTB + TAIL_BASE_B + (tid - 400) * 16,
                                 src + s * 7200 + 6400 + (tid - 400) * 16);
    }
}

__global__ __launch_bounds__(CTHREADS, 2) void col_kernel(
    const int* __restrict__ matrix,
    const int* __restrict__ mask,
    float* __restrict__ sout)
{
    __shared__ __align__(16) __half Tsh[2][2 * BUFH];
    __shared__ __align__(16) int codes[2][256];

    const int jbase = blockIdx.x * 128;
    const int i0 = blockIdx.y * IT;
    const int i1 = min(i0 + IT, NN);
    const int nst = (i1 - i0) >> 1;
    const int tid = threadIdx.x;
    const int w = tid >> 5, lane = tid & 31;
    const int g = lane >> 2, p = lane & 3;

    float2 a0[8];
    float2 a1[2];
    #pragma unroll
    for (int q = 0; q < 8; q++) a0[q] = make_float2(0.f, 0.f);
    a1[0] = make_float2(0.f, 0.f);
    a1[1] = make_float2(0.f, 0.f);

    // zero sentinel words (per buffer, per slot)
    if (tid < 128) {
        int b = tid >> 6, rest = tid & 63, s = rest >> 5, k = rest & 31;
        ((unsigned*)&Tsh[b][0])[s * 1840 + 1600 + k] = 0u;   // main sentinel 128B
    }
    if (tid < 16) {
        int b = tid >> 3, s = (tid >> 2) & 1, k = tid & 3;
        ((unsigned*)&Tsh[b][0])[s * 1840 + 1832 + k] = 0u;   // tail sentinel 16B
    }

    const char* tb0 = (const char*)&Tsh[0][0];
    const char* tb1 = (const char*)&Tsh[1][0];
    const unsigned ts0 = (unsigned)__cvta_generic_to_shared(tb0);
    const unsigned ts1 = (unsigned)__cvta_generic_to_shared(tb1);

    const int2* m2 = (const int2*)matrix;
    const int2* k2 = (const int2*)mask;

    stage2(ts0, (const char*)(g_Th + (size_t)i0 * TPI), tid);
    asm volatile("cp.async.commit_group;");

    int pcode = 0;
    if (tid < 256) {
        int ii = tid >> 7, jj = tid & 127;
        size_t idx = (size_t)(i0 + ii) * NN + jbase + jj;
        int2 tt = m2[idx];
        int2 km = k2[idx];
        pcode = (km.x ? (tt.x << 7) : (int)MAIN_SENT_B) |
                ((km.y ? (tt.y << 7) : (int)MAIN_SENT_B) << 16);
    }

    for (int st = 0; st < nst; st++) {
        const int buf = st & 1;
        const char* Tbb = buf ? tb1 : tb0;

        asm volatile("cp.async.wait_group 0;" ::: "memory");
        if (tid < 256) codes[buf][tid] = pcode;
        __syncthreads();

        if (st + 1 < nst) {
            const int inext = i0 + 2 * (st + 1);
            stage2(buf ? ts0 : ts1, (const char*)(g_Th + (size_t)inext * TPI), tid);
            asm volatile("cp.async.commit_group;");
            if (tid < 256) {
                int ii = tid >> 7, jj = tid & 127;
                size_t idx = (size_t)(inext + ii) * NN + jbase + jj;
                int2 tt = m2[idx];
                int2 km = k2[idx];
                pcode = (km.x ? (tt.x << 7) : (int)MAIN_SENT_B) |
                        ((km.y ? (tt.y << 7) : (int)MAIN_SENT_B) << 16);
            }
        }

        #pragma unroll
        for (int s2 = 0; s2 < 2; s2++) {
            const char* Tb = Tbb + s2 * SLOTB;
            const int4* c4 = (const int4*)(codes[buf] + s2 * 128 + w * 8);
            int4 cA = c4[0];          // broadcast LDS.128
            int4 cB = c4[1];
            const char* mb = Tb + lane * 4;

            unsigned cc, o0, o1;
            __half2 h0, h1;
            float2 v;
            #define GATHER_MAIN(CQ, Q) \
                cc = (unsigned)(CQ); \
                o0 = cc & 0xFFFFu; o1 = cc >> 16; \
                h0 = *(const __half2*)(mb + o0); \
                h1 = *(const __half2*)(mb + o1); \
                v = __half22float2(__hadd2(h0, h1)); \
                a0[Q].x += v.x; a0[Q].y += v.y;
            GATHER_MAIN(cA.x, 0) GATHER_MAIN(cA.y, 1)
            GATHER_MAIN(cA.z, 2) GATHER_MAIN(cA.w, 3)
            GATHER_MAIN(cB.x, 4) GATHER_MAIN(cB.y, 5)
            GATHER_MAIN(cB.z, 6) GATHER_MAIN(cB.w, 7)
            #undef GATHER_MAIN

            // tail: slots s = r*8+g; lane reads pair p of row t(s)
            unsigned cq[8] = {(unsigned)cA.x, (unsigned)cA.y, (unsigned)cA.z, (unsigned)cA.w,
                              (unsigned)cB.x, (unsigned)cB.y, (unsigned)cB.z, (unsigned)cB.w};
            #pragma unroll
            for (int r = 0; r < 2; r++) {
                int s = r * 8 + g;
                unsigned c32 = cq[s >> 1];
                unsigned c16 = (s & 1) ? (c32 >> 16) : (c32 & 0xFFFFu);
                unsigned t = c16 >> 7;           // type, or 50 for sentinel
                float2 tv = __half22float2(*(const __half2*)(Tb + TAIL_BASE_B + t * 16 + p * 4));
                a1[r].x += tv.x;
                a1[r].y += tv.y;
            }
        }
    }

    // epilogue
    #pragma unroll
    for (int q = 0; q < 8; q++) {
        int j = jbase + w * 8 + q;
        float* base = sout + (size_t)j * DOUT;
        asm volatile("red.global.add.v2.f32 [%0], {%1, %2};"
                     :: "l"(base + 2 * lane), "f"(a0[q].x), "f"(a0[q].y) : "memory");
    }
    if (p < 3) {
        #pragma unroll
        for (int r = 0; r < 2; r++) {
            int s = r * 8 + g;
            int j = jbase + w * 8 + (s >> 1);
            float* base = sout + (size_t)j * DOUT + 64 + 2 * p;
            asm volatile("red.global.add.v2.f32 [%0], {%1, %2};"
                         :: "l"(base), "f"(a1[r].x), "f"(a1[r].y) : "memory");
        }
    }
}

// ---------------------------------------------------------------------------
extern "C" void kernel_launch(void* const* d_in, const int* in_sizes, int n_in,
                              void* d_out, int out_size)
{
    const float* h      = (const float*)d_in[0];
    const float* emb    = (const float*)d_in[1];
    const float* W      = (const float*)d_in[2];
    const float* bvec   = (const float*)d_in[3];
    const int*   matrix = (const int*)d_in[4];
    const int*   mask   = (const int*)d_in[5];
    float* out = (float*)d_out;

    row_kernel<<<NN / 4, 640>>>(h, emb, W, bvec, matrix, mask, out);
    col_kernel<<<dim3(8, 37), CTHREADS>>>(matrix, mask, out + NN * DOUT);
}

// round 14
// speedup vs baseline: 1.1941x; 1.1852x over previous
#include <cuda_runtime.h>
#include <cuda_fp16.h>
#include <cstdint>

#define NN 1024
#define H2 60
#define DEP 10
#define DOUT 70
#define NTYPE 50

// fp16 T layout per i: main = dims 0..63, 50 rows x 64 halfs (128B rows);
// tail = dims 64..69 (+2 pad), 50 rows x 8 halfs (16B rows).
#define TPI 3600
#define BUFH 3680             // halfs per i-slot in SMEM (7360B)
#define SLOTB 7360
#define MAIN_SENT_B 6400      // byte offset of main sentinel row within slot
#define TAIL_BASE_B 6528

__device__ __half g_Th[NN * TPI];    // 7.37 MB — L2-resident
__device__ int    g_codes[NN * NN];  // 4 MB: packed (k0,k1) row offsets per (i,j)

// tanh(x) = 1 - 2/(exp(2x)+1), via SFU ex2/rcp.
__device__ __forceinline__ float fast_tanh(float x) {
    float e, r;
    asm("ex2.approx.f32 %0, %1;" : "=f"(e) : "f"(x * 2.885390082f));
    asm("rcp.approx.f32 %0, %1;" : "=f"(r) : "f"(e + 1.0f));
    return fmaf(-2.0f, r, 1.0f);
}

// ---------------------------------------------------------------------------
// Kernel R: 640 threads = 4 groups x 160. Block computes eWb into SMEM, then
// each group owns row i = B*4+grp: histogram + CODE EMISSION (packed offsets
// for col_kernel), hW, T table (fp16 split), s_in, zero s_out.
// ---------------------------------------------------------------------------
__global__ __launch_bounds__(640) void row_kernel(
    const float* __restrict__ h,
    const float* __restrict__ emb,
    const float* __restrict__ W,
    const float* __restrict__ bvec,
    const int* __restrict__ matrix,
    const int* __restrict__ mask,
    float* __restrict__ out)
{
    const int tid = threadIdx.x;
    const int grp = tid / 160;
    const int gtid = tid - grp * 160;
    const int w = tid >> 5;
    const int lane = tid & 31;
    const int i = blockIdx.x * 4 + grp;
    const int bar = grp + 1;

    __shared__ int   cnt[20][64];
    __shared__ float sP[4][72];
    __shared__ float ewb[NTYPE * DOUT];

    cnt[w][lane] = 0;
    cnt[w][lane + 32] = 0;
    for (int k = tid; k < NTYPE * DOUT; k += 640) {
        int t = k / DOUT, f = k - t * DOUT;
        float s = __ldg(bvec + f);
        #pragma unroll
        for (int c = 0; c < DEP; c++)
            s = fmaf(__ldg(emb + t * DEP + c), __ldg(W + (H2 + c) * DOUT + f), s);
        ewb[k] = s;
    }
    __syncthreads();

    // histogram + code emission (int4 loads = 2 j's per iteration)
    {
        const int4* m4 = (const int4*)(matrix + (size_t)i * 2 * NN);
        const int4* k4 = (const int4*)(mask   + (size_t)i * 2 * NN);
        int2* c2 = (int2*)(g_codes + (size_t)i * NN);
        for (int e = gtid; e < 512; e += 160) {
            int4 mm = m4[e];
            int4 kk = k4[e];
            if (kk.x) atomicAdd(&cnt[w][mm.x], 1);
            if (kk.y) atomicAdd(&cnt[w][mm.y], 1);
            if (kk.z) atomicAdd(&cnt[w][mm.z], 1);
            if (kk.w) atomicAdd(&cnt[w][mm.w], 1);
            int c0 = (kk.x ? (mm.x << 7) : MAIN_SENT_B) |
                     ((kk.y ? (mm.y << 7) : MAIN_SENT_B) << 16);
            int c1 = (kk.z ? (mm.z << 7) : MAIN_SENT_B) |
                     ((kk.w ? (mm.w << 7) : MAIN_SENT_B) << 16);
            c2[e] = make_int2(c0, c1);
        }
    }
    asm volatile("bar.sync %0, 160;" :: "r"(bar) : "memory");

    const int b0 = grp * 5;
    if (gtid < NTYPE) {
        int s = cnt[b0][gtid] + cnt[b0 + 1][gtid] + cnt[b0 + 2][gtid]
              + cnt[b0 + 3][gtid] + cnt[b0 + 4][gtid];
        cnt[b0][gtid] = s;
    }
    asm volatile("bar.sync %0, 160;" :: "r"(bar) : "memory");

    const int shalf = gtid / DOUT;
    const int f = gtid - shalf * DOUT;
    float acc = 0.f;
    if (shalf < 2) {
        float hw = 0.f;
        #pragma unroll 6
        for (int c = 0; c < H2; c++)
            hw = fmaf(__ldg(h + i * H2 + c), __ldg(W + c * DOUT + f), hw);

        __half* Tb = g_Th + (size_t)i * TPI;
        const int t0 = shalf * 25, t1 = t0 + 25;
        #pragma unroll 5
        for (int t = t0; t < t1; t++) {
            float v = fast_tanh(hw + ewb[t * DOUT + f]);
            if (f < 64) Tb[t * 64 + f] = __float2half_rn(v);
            else        Tb[3200 + t * 8 + (f - 64)] = __float2half_rn(v);
            acc = fmaf((float)cnt[b0][t], v, acc);
        }
        if (shalf == 1) sP[grp][f] = acc;
    }
    asm volatile("bar.sync %0, 160;" :: "r"(bar) : "memory");
    if (shalf == 0) {
        out[i * DOUT + f] = acc + sP[grp][f];   // s_in (fp32)
        out[NN * DOUT + i * DOUT + f] = 0.f;    // zero s_out for kernel C
    }
}

// ---------------------------------------------------------------------------
// Kernel C: s_out gather — R9-proven IPS=2 static-SMEM structure, with codes
// PRECOMPUTED in g_codes (1 LDG.32 per thread per stage instead of the
// matrix/mask prefetch block). Everything else identical to the 27.1us R9.
// ---------------------------------------------------------------------------
#define IT 28
#define CTHREADS 512

__device__ __forceinline__ void cp16(unsigned dst, const void* src) {
    asm volatile("cp.async.cg.shared.global [%0], [%1], 16;" :: "r"(dst), "l"(src));
}

__device__ __forceinline__ void stage2(unsigned dst, const char* src, int tid) {
    #pragma unroll
    for (int s = 0; s < 2; s++) {
        if (tid < 400) cp16(dst + s * SLOTB + tid * 16, src + s * 7200 + tid * 16);
        else if (tid < 450) cp16(dst + s * SLOTB + TAIL_BASE_B + (tid - 400) * 16,
                                 src + s * 7200 + 6400 + (tid - 400) * 16);
    }
}

__global__ __launch_bounds__(CTHREADS, 2) void col_kernel(
    float* __restrict__ sout)
{
    __shared__ __align__(16) __half Tsh[2][2 * BUFH];
    __shared__ int codes[2][256];

    const int jbase = blockIdx.x * 128;
    const int i0 = blockIdx.y * IT;
    const int i1 = min(i0 + IT, NN);
    const int nst = (i1 - i0) >> 1;
    const int tid = threadIdx.x;
    const int w = tid >> 5, lane = tid & 31;
    const int g = lane >> 2, p = lane & 3;

    float2 a0[8];
    float2 a1[2];
    #pragma unroll
    for (int q = 0; q < 8; q++) a0[q] = make_float2(0.f, 0.f);
    a1[0] = make_float2(0.f, 0.f);
    a1[1] = make_float2(0.f, 0.f);

    if (tid < 128) {
        int b = tid >> 6, rest = tid & 63, s = rest >> 5, k = rest & 31;
        ((unsigned*)&Tsh[b][0])[s * 1840 + 1600 + k] = 0u;   // main sentinel 128B
    }
    if (tid < 16) {
        int b = tid >> 3, s = (tid >> 2) & 1, k = tid & 3;
        ((unsigned*)&Tsh[b][0])[s * 1840 + 1832 + k] = 0u;   // tail sentinel 16B
    }

    const char* tb0 = (const char*)&Tsh[0][0];
    const char* tb1 = (const char*)&Tsh[1][0];
    const unsigned ts0 = (unsigned)__cvta_generic_to_shared(tb0);
    const unsigned ts1 = (unsigned)__cvta_generic_to_shared(tb1);

    stage2(ts0, (const char*)(g_Th + (size_t)i0 * TPI), tid);
    asm volatile("cp.async.commit_group;");

    int pcode = 0;
    if (tid < 256) {
        int ii = tid >> 7, jj = tid & 127;
        pcode = __ldg(g_codes + (size_t)(i0 + ii) * NN + jbase + jj);
    }

    for (int st = 0; st < nst; st++) {
        const int buf = st & 1;
        const char* Tbb = buf ? tb1 : tb0;

        asm volatile("cp.async.wait_group 0;" ::: "memory");
        if (tid < 256) codes[buf][tid] = pcode;
        __syncthreads();

        if (st + 1 < nst) {
            const int inext = i0 + 2 * (st + 1);
            stage2(buf ? ts0 : ts1, (const char*)(g_Th + (size_t)inext * TPI), tid);
            asm volatile("cp.async.commit_group;");
            if (tid < 256) {
                int ii = tid >> 7, jj = tid & 127;
                pcode = __ldg(g_codes + (size_t)(inext + ii) * NN + jbase + jj);
            }
        }

        #pragma unroll
        for (int s2 = 0; s2 < 2; s2++) {
            const char* Tb = Tbb + s2 * SLOTB;
            const int* cb = codes[buf] + s2 * 128 + w * 8;
            const char* mb = Tb + lane * 4;
            #pragma unroll
            for (int q = 0; q < 8; q++) {
                unsigned cc = (unsigned)cb[q];   // warp-uniform broadcast
                unsigned o0 = cc & 0xFFFFu;
                unsigned o1 = cc >> 16;
                __half2 h0 = *(const __half2*)(mb + o0);
                __half2 h1 = *(const __half2*)(mb + o1);
                float2 v = __half22float2(__hadd2(h0, h1));
                a0[q].x += v.x;
                a0[q].y += v.y;
            }
            #pragma unroll
            for (int r = 0; r < 2; r++) {
                int s = r * 8 + g;
                unsigned cc = (unsigned)cb[s >> 1];
                unsigned c16 = (s & 1) ? (cc >> 16) : (cc & 0xFFFFu);
                unsigned t = c16 >> 7;           // type, or 50 for sentinel
                float2 v = __half22float2(*(const __half2*)(Tb + TAIL_BASE_B + t * 16 + p * 4));
                a1[r].x += v.x;
                a1[r].y += v.y;
            }
        }
    }

    #pragma unroll
    for (int q = 0; q < 8; q++) {
        int j = jbase + w * 8 + q;
        float* base = sout + (size_t)j * DOUT;
        asm volatile("red.global.add.v2.f32 [%0], {%1, %2};"
                     :: "l"(base + 2 * lane), "f"(a0[q].x), "f"(a0[q].y) : "memory");
    }
    if (p < 3) {
        #pragma unroll
        for (int r = 0; r < 2; r++) {
            int s = r * 8 + g;
            int j = jbase + w * 8 + (s >> 1);
            float* base = sout + (size_t)j * DOUT + 64 + 2 * p;
            asm volatile("red.global.add.v2.f32 [%0], {%1, %2};"
                         :: "l"(base), "f"(a1[r].x), "f"(a1[r].y) : "memory");
        }
    }
}

// ---------------------------------------------------------------------------
extern "C" void kernel_launch(void* const* d_in, const int* in_sizes, int n_in,
                              void* d_out, int out_size)
{
    const float* h      = (const float*)d_in[0];
    const float* emb    = (const float*)d_in[1];
    const float* W      = (const float*)d_in[2];
    const float* bvec   = (const float*)d_in[3];
    const int*   matrix = (const int*)d_in[4];
    const int*   mask   = (const int*)d_in[5];
    float* out = (float*)d_out;

    row_kernel<<<NN / 4, 640>>>(h, emb, W, bvec, matrix, mask, out);
    col_kernel<<<dim3(8, 37), CTHREADS>>>(out + NN * DOUT);
}

// round 15
// speedup vs baseline: 1.1960x; 1.0016x over previous
#include <cuda_runtime.h>
#include <cuda_fp16.h>
#include <cstdint>

#define NN 1024
#define H2 60
#define DEP 10
#define DOUT 70
#define NTYPE 50

// fp16 T layout per i: main = dims 0..63, 50 rows x 64 halfs (128B rows);
// tail = dims 64..69 (+2 pad), 50 rows x 8 halfs (16B rows).
#define TPI 3600
#define BUFH 3680             // halfs per i-slot in SMEM (7360B)
#define SLOTB 7360
#define MAIN_SENT_B 6400      // byte offset of main sentinel row within slot
#define TAIL_BASE_B 6528

__device__ __half g_Th[NN * TPI];    // 7.37 MB — L2-resident
__device__ int    g_codes[NN * NN];  // 4 MB: packed (k0,k1) row offsets per (i,j)
__device__ float  g_eWb[NTYPE * DOUT];

// tanh(x) = 1 - 2/(exp(2x)+1), via SFU ex2/rcp.
__device__ __forceinline__ float fast_tanh(float x) {
    float e, r;
    asm("ex2.approx.f32 %0, %1;" : "=f"(e) : "f"(x * 2.885390082f));
    asm("rcp.approx.f32 %0, %1;" : "=f"(r) : "f"(e + 1.0f));
    return fmaf(-2.0f, r, 1.0f);
}

// ---------------------------------------------------------------------------
// Kernel E: eWb = b + emb @ W[H2:]. ONE block, SMEM-staged inputs so the
// cold-miss latency is paid once in parallel, not serially per output.
// ---------------------------------------------------------------------------
__global__ __launch_bounds__(512) void ewb_kernel(
    const float* __restrict__ emb,
    const float* __restrict__ W,
    const float* __restrict__ bvec)
{
    __shared__ float esh[NTYPE * DEP];   // 500
    __shared__ float wsh[DEP * DOUT];    // 700
    __shared__ float bsh[DOUT];
    const int tid = threadIdx.x;

    if (tid < NTYPE * DEP) esh[tid] = emb[tid];
    if (tid >= 512 - DOUT) bsh[tid - (512 - DOUT)] = bvec[tid - (512 - DOUT)];
    for (int k = tid; k < DEP * DOUT; k += 512) wsh[k] = W[H2 * DOUT + k];
    __syncthreads();

    for (int k = tid; k < NTYPE * DOUT; k += 512) {
        int t = k / DOUT, f = k - t * DOUT;
        float s = bsh[f];
        #pragma unroll
        for (int c = 0; c < DEP; c++)
            s = fmaf(esh[t * DEP + c], wsh[c * DOUT + f], s);
        g_eWb[k] = s;
    }
}

// ---------------------------------------------------------------------------
// Kernel R (R10-measured 8us form + code emission): 640 threads = 4 groups
// x 160 (5 warps), named barriers. Histogram + code emission, hW via __ldg,
// eWb via __ldg(g_eWb), T table (fp16 split), s_in, zero s_out.
// ---------------------------------------------------------------------------
__global__ __launch_bounds__(640) void row_kernel(
    const float* __restrict__ h,
    const float* __restrict__ W,
    const int* __restrict__ matrix,
    const int* __restrict__ mask,
    float* __restrict__ out)
{
    const int tid = threadIdx.x;
    const int grp = tid / 160;
    const int gtid = tid - grp * 160;
    const int w = tid >> 5;
    const int lane = tid & 31;
    const int i = blockIdx.x * 4 + grp;
    const int bar = grp + 1;

    __shared__ int   cnt[20][64];
    __shared__ float sP[4][72];

    cnt[w][lane] = 0;
    cnt[w][lane + 32] = 0;
    asm volatile("bar.sync %0, 160;" :: "r"(bar) : "memory");

    // histogram + code emission (int4 loads = 2 j's per iteration)
    {
        const int4* m4 = (const int4*)(matrix + (size_t)i * 2 * NN);
        const int4* k4 = (const int4*)(mask   + (size_t)i * 2 * NN);
        int2* c2 = (int2*)(g_codes + (size_t)i * NN);
        for (int e = gtid; e < 512; e += 160) {
            int4 mm = m4[e];
            int4 kk = k4[e];
            if (kk.x) atomicAdd(&cnt[w][mm.x], 1);
            if (kk.y) atomicAdd(&cnt[w][mm.y], 1);
            if (kk.z) atomicAdd(&cnt[w][mm.z], 1);
            if (kk.w) atomicAdd(&cnt[w][mm.w], 1);
            int c0 = (kk.x ? (mm.x << 7) : MAIN_SENT_B) |
                     ((kk.y ? (mm.y << 7) : MAIN_SENT_B) << 16);
            int c1 = (kk.z ? (mm.z << 7) : MAIN_SENT_B) |
                     ((kk.w ? (mm.w << 7) : MAIN_SENT_B) << 16);
            c2[e] = make_int2(c0, c1);
        }
    }
    asm volatile("bar.sync %0, 160;" :: "r"(bar) : "memory");

    const int b0 = grp * 5;
    if (gtid < NTYPE) {
        int s = cnt[b0][gtid] + cnt[b0 + 1][gtid] + cnt[b0 + 2][gtid]
              + cnt[b0 + 3][gtid] + cnt[b0 + 4][gtid];
        cnt[b0][gtid] = s;
    }
    asm volatile("bar.sync %0, 160;" :: "r"(bar) : "memory");

    const int shalf = gtid / DOUT;
    const int f = gtid - shalf * DOUT;
    float acc = 0.f;
    if (shalf < 2) {
        float hw = 0.f;
        #pragma unroll 6
        for (int c = 0; c < H2; c++)
            hw = fmaf(__ldg(h + i * H2 + c), __ldg(W + c * DOUT + f), hw);

        __half* Tb = g_Th + (size_t)i * TPI;
        const int t0 = shalf * 25, t1 = t0 + 25;
        #pragma unroll 5
        for (int t = t0; t < t1; t++) {
            float v = fast_tanh(hw + __ldg(g_eWb + t * DOUT + f));
            if (f < 64) Tb[t * 64 + f] = __float2half_rn(v);
            else        Tb[3200 + t * 8 + (f - 64)] = __float2half_rn(v);
            acc = fmaf((float)cnt[b0][t], v, acc);
        }
        if (shalf == 1) sP[grp][f] = acc;
    }
    asm volatile("bar.sync %0, 160;" :: "r"(bar) : "memory");
    if (shalf == 0) {
        out[i * DOUT + f] = acc + sP[grp][f];   // s_in (fp32)
        out[NN * DOUT + i * DOUT + f] = 0.f;    // zero s_out for kernel C
    }
}

// ---------------------------------------------------------------------------
// Kernel C: s_out gather — UNCHANGED from R14 (25.4us, protect it).
// ---------------------------------------------------------------------------
#define IT 28
#define CTHREADS 512

__device__ __forceinline__ void cp16(unsigned dst, const void* src) {
    asm volatile("cp.async.cg.shared.global [%0], [%1], 16;" :: "r"(dst), "l"(src));
}

__device__ __forceinline__ void stage2(unsigned dst, const char* src, int tid) {
    #pragma unroll
    for (int s = 0; s < 2; s++) {
        if (tid < 400) cp16(dst + s * SLOTB + tid * 16, src + s * 7200 + tid * 16);
        else if (tid < 450) cp16(dst + s * SLOTB + TAIL_BASE_B + (tid - 400) * 16,
                                 src + s * 7200 + 6400 + (tid - 400) * 16);
    }
}

__global__ __launch_bounds__(CTHREADS, 2) void col_kernel(
    float* __restrict__ sout)
{
    __shared__ __align__(16) __half Tsh[2][2 * BUFH];
    __shared__ int codes[2][256];

    const int jbase = blockIdx.x * 128;
    const int i0 = blockIdx.y * IT;
    const int i1 = min(i0 + IT, NN);
    const int nst = (i1 - i0) >> 1;
    const int tid = threadIdx.x;
    const int w = tid >> 5, lane = tid & 31;
    const int g = lane >> 2, p = lane & 3;

    float2 a0[8];
    float2 a1[2];
    #pragma unroll
    for (int q = 0; q < 8; q++) a0[q] = make_float2(0.f, 0.f);
    a1[0] = make_float2(0.f, 0.f);
    a1[1] = make_float2(0.f, 0.f);

    if (tid < 128) {
        int b = tid >> 6, rest = tid & 63, s = rest >> 5, k = rest & 31;
        ((unsigned*)&Tsh[b][0])[s * 1840 + 1600 + k] = 0u;   // main sentinel 128B
    }
    if (tid < 16) {
        int b = tid >> 3, s = (tid >> 2) & 1, k = tid & 3;
        ((unsigned*)&Tsh[b][0])[s * 1840 + 1832 + k] = 0u;   // tail sentinel 16B
    }

    const char* tb0 = (const char*)&Tsh[0][0];
    const char* tb1 = (const char*)&Tsh[1][0];
    const unsigned ts0 = (unsigned)__cvta_generic_to_shared(tb0);
    const unsigned ts1 = (unsigned)__cvta_generic_to_shared(tb1);

    stage2(ts0, (const char*)(g_Th + (size_t)i0 * TPI), tid);
    asm volatile("cp.async.commit_group;");

    int pcode = 0;
    if (tid < 256) {
        int ii = tid >> 7, jj = tid & 127;
        pcode = __ldg(g_codes + (size_t)(i0 + ii) * NN + jbase + jj);
    }

    for (int st = 0; st < nst; st++) {
        const int buf = st & 1;
        const char* Tbb = buf ? tb1 : tb0;

        asm volatile("cp.async.wait_group 0;" ::: "memory");
        if (tid < 256) codes[buf][tid] = pcode;
        __syncthreads();

        if (st + 1 < nst) {
            const int inext = i0 + 2 * (st + 1);
            stage2(buf ? ts0 : ts1, (const char*)(g_Th + (size_t)inext * TPI), tid);
            asm volatile("cp.async.commit_group;");
            if (tid < 256) {
                int ii = tid >> 7, jj = tid & 127;
                pcode = __ldg(g_codes + (size_t)(inext + ii) * NN + jbase + jj);
            }
        }

        #pragma unroll
        for (int s2 = 0; s2 < 2; s2++) {
            const char* Tb = Tbb + s2 * SLOTB;
            const int* cb = codes[buf] + s2 * 128 + w * 8;
            const char* mb = Tb + lane * 4;
            #pragma unroll
            for (int q = 0; q < 8; q++) {
                unsigned cc = (unsigned)cb[q];   // warp-uniform broadcast
                unsigned o0 = cc & 0xFFFFu;
                unsigned o1 = cc >> 16;
                __half2 h0 = *(const __half2*)(mb + o0);
                __half2 h1 = *(const __half2*)(mb + o1);
                float2 v = __half22float2(__hadd2(h0, h1));
                a0[q].x += v.x;
                a0[q].y += v.y;
            }
            #pragma unroll
            for (int r = 0; r < 2; r++) {
                int s = r * 8 + g;
                unsigned cc = (unsigned)cb[s >> 1];
                unsigned c16 = (s & 1) ? (cc >> 16) : (cc & 0xFFFFu);
                unsigned t = c16 >> 7;           // type, or 50 for sentinel
                float2 v = __half22float2(*(const __half2*)(Tb + TAIL_BASE_B + t * 16 + p * 4));
                a1[r].x += v.x;
                a1[r].y += v.y;
            }
        }
    }

    #pragma unroll
    for (int q = 0; q < 8; q++) {
        int j = jbase + w * 8 + q;
        float* base = sout + (size_t)j * DOUT;
        asm volatile("red.global.add.v2.f32 [%0], {%1, %2};"
                     :: "l"(base + 2 * lane), "f"(a0[q].x), "f"(a0[q].y) : "memory");
    }
    if (p < 3) {
        #pragma unroll
        for (int r = 0; r < 2; r++) {
            int s = r * 8 + g;
            int j = jbase + w * 8 + (s >> 1);
            float* base = sout + (size_t)j * DOUT + 64 + 2 * p;
            asm volatile("red.global.add.v2.f32 [%0], {%1, %2};"
                         :: "l"(base), "f"(a1[r].x), "f"(a1[r].y) : "memory");
        }
    }
}

// ---------------------------------------------------------------------------
extern "C" void kernel_launch(void* const* d_in, const int* in_sizes, int n_in,
                              void* d_out, int out_size)
{
    const float* h      = (const float*)d_in[0];
    const float* emb    = (const float*)d_in[1];
    const float* W      = (const float*)d_in[2];
    const float* bvec   = (const float*)d_in[3];
    const int*   matrix = (const int*)d_in[4];
    const int*   mask   = (const int*)d_in[5];
    float* out = (float*)d_out;

    ewb_kernel<<<1, 512>>>(emb, W, bvec);
    row_kernel<<<NN / 4, 640>>>(h, W, matrix, mask, out);
    col_kernel<<<dim3(8, 37), CTHREADS>>>(out + NN * DOUT);
}